// round 3
// baseline (speedup 1.0000x reference)
#include <cuda_runtime.h>
#include <cuda_bf16.h>
#include <math.h>

// ---------------- problem constants ----------------
#define B_    64
#define HID_  2048
#define NH_   32
#define NKV_  8
#define HD_   64
#define G_    4          // NH/NKV
#define BS_   16
#define MAXB_ 128
#define MAXKV_ 2048
#define QKVN_ 3072       // NH*HD + 2*NKV*HD
#define SCALE_ 0.125f    // 64^-0.5

// ---------------- scratch: device globals only (no allocation APIs) --------
__device__ float g_qkv[B_ * QKVN_];          // 64x3072 qkv projection
__device__ float g_q  [B_ * NH_ * HD_];      // rmsnorm+rope'd q
__device__ float g_k  [B_ * NKV_ * HD_];     // rmsnorm+rope'd new k
__device__ float g_att[B_ * NH_ * HD_];      // attention output (64x2048)

// ---------------- zero helpers ----------------
__global__ void zero_qkv_kernel() {
    int i = blockIdx.x * 256 + threadIdx.x;
    if (i < B_ * QKVN_) g_qkv[i] = 0.f;
}
__global__ void zero_out_kernel(float* __restrict__ p, int n) {
    int i = blockIdx.x * 256 + threadIdx.x;
    if (i < n) p[i] = 0.f;
}

// ---------------- GEMM body: C(64xN) += A(64xK) * B(KxN), K-split atomics ---
// BM=64 BN=64 BK=16, 256 threads, 4x4 micro-tile
__device__ __forceinline__ void gemm_body(
    const float* __restrict__ A, const float* __restrict__ B, float* __restrict__ C,
    int N, int K, int kchunk)
{
    __shared__ float As[16][68];   // [k][m]
    __shared__ float Bs[16][64];   // [k][n]

    int n0 = blockIdx.x * 64;
    int k0 = blockIdx.y * kchunk;
    int kend = k0 + kchunk;

    int t  = threadIdx.x;
    int tx = t & 15, ty = t >> 4;
    int r0 = ty * 4, c0 = tx * 4;

    int lm  = t >> 2;          // A load: row 0..63
    int lkq = (t & 3) * 4;     // A load: k offset 0,4,8,12
    int lk  = t >> 4;          // B load: k 0..15
    int lnq = (t & 15) * 4;    // B load: n offset

    float acc[4][4];
#pragma unroll
    for (int i = 0; i < 4; i++)
#pragma unroll
        for (int j = 0; j < 4; j++) acc[i][j] = 0.f;

    for (int kb = k0; kb < kend; kb += 16) {
        float4 av = *(const float4*)&A[(size_t)lm * K + kb + lkq];
        As[lkq + 0][lm] = av.x;
        As[lkq + 1][lm] = av.y;
        As[lkq + 2][lm] = av.z;
        As[lkq + 3][lm] = av.w;
        *(float4*)&Bs[lk][lnq] = *(const float4*)&B[(size_t)(kb + lk) * N + n0 + lnq];
        __syncthreads();
#pragma unroll
        for (int kk = 0; kk < 16; kk++) {
            float4 a  = *(const float4*)&As[kk][r0];
            float4 bv = *(const float4*)&Bs[kk][c0];
            acc[0][0] += a.x * bv.x; acc[0][1] += a.x * bv.y; acc[0][2] += a.x * bv.z; acc[0][3] += a.x * bv.w;
            acc[1][0] += a.y * bv.x; acc[1][1] += a.y * bv.y; acc[1][2] += a.y * bv.z; acc[1][3] += a.y * bv.w;
            acc[2][0] += a.z * bv.x; acc[2][1] += a.z * bv.y; acc[2][2] += a.z * bv.z; acc[2][3] += a.z * bv.w;
            acc[3][0] += a.w * bv.x; acc[3][1] += a.w * bv.y; acc[3][2] += a.w * bv.z; acc[3][3] += a.w * bv.w;
        }
        __syncthreads();
    }

#pragma unroll
    for (int i = 0; i < 4; i++)
#pragma unroll
        for (int j = 0; j < 4; j++)
            atomicAdd(&C[(size_t)(r0 + i) * N + n0 + c0 + j], acc[i][j]);
}

__global__ __launch_bounds__(256) void gemm_qkv_kernel(
    const float* __restrict__ A, const float* __restrict__ Bm)
{
    gemm_body(A, Bm, g_qkv, QKVN_, HID_, HID_ / 4);
}
__global__ __launch_bounds__(256) void gemm_out_kernel(
    const float* __restrict__ Bm, float* __restrict__ C)
{
    gemm_body(g_att, Bm, C, HID_, NH_ * HD_, (NH_ * HD_) / 4);
}

// ---------------- RMSNorm + RoPE for q (32 heads) and k (8 heads) ----------
__global__ __launch_bounds__(256) void prep_kernel(
    const int* __restrict__ positions,
    const float* __restrict__ qw, const float* __restrict__ kw)
{
    int b = blockIdx.x;
    int t = threadIdx.x, w = t >> 5, lane = t & 31;
    __shared__ float cs[32], sn[32];

    int pos = positions[b];
    if (t < 32) {
        // inv_freq[j] = 1e6^(-j/32); ln(1e6)=13.815510557964274
        double invf = exp(-(double)t * (13.815510557964274 / 32.0));
        double ang  = (double)pos * invf;
        cs[t] = (float)cos(ang);
        sn[t] = (float)sin(ang);
    }
    __syncthreads();

    const float* row = g_qkv + (size_t)b * QKVN_;
    for (int h = w; h < NH_ + NKV_; h += 8) {
        bool isq = (h < NH_);
        const float* src = isq ? row + h * HD_ : row + NH_ * HD_ + (h - NH_) * HD_;
        float x1 = src[lane], x2 = src[lane + 32];
        float ss = x1 * x1 + x2 * x2;
#pragma unroll
        for (int o = 16; o; o >>= 1) ss += __shfl_xor_sync(0xffffffffu, ss, o);
        float inv = rsqrtf(ss * (1.f / 64.f) + 1e-5f);
        const float* lw = isq ? qw : kw;
        x1 *= inv * lw[lane];
        x2 *= inv * lw[lane + 32];
        float c = cs[lane], s = sn[lane];
        float y1 = x1 * c - x2 * s;
        float y2 = x2 * c + x1 * s;
        float* dst = isq ? g_q + ((size_t)b * NH_ + h) * HD_
                         : g_k + ((size_t)b * NKV_ + (h - NH_)) * HD_;
        dst[lane]      = y1;
        dst[lane + 32] = y2;
    }
}

// ---------------- paged GQA attention: one CTA per (kv-head, batch) --------
// new k/v at position ctx-1 read from g_k / g_qkv (never scatter into caches)
__global__ __launch_bounds__(256) void attn_kernel(
    const float* __restrict__ kc, const float* __restrict__ vc,
    const int* __restrict__ ctxlens, const int* __restrict__ btab)
{
    __shared__ float sc[G_][MAXKV_];     // 32 KB scores/probs
    __shared__ float obuf[8][G_][HD_];   // 8 KB per-warp partial outputs
    __shared__ float wmax[8][G_];
    __shared__ float gmax[G_];
    __shared__ float gsum[G_];
    __shared__ int   sbt[MAXB_];

    int kv = blockIdx.x, b = blockIdx.y;
    int t = threadIdx.x, w = t >> 5, lane = t & 31;
    int half = lane >> 4, l16 = lane & 15;
    int ctx = ctxlens[b];
    ctx = ctx < 1 ? 1 : (ctx > MAXKV_ ? MAXKV_ : ctx);   // defensive clamp

    if (t < MAXB_) sbt[t] = btab[b * MAXB_ + t];
    if (t < G_)    gsum[t] = 0.f;

    // per-lane q chunks (float4, 16 lanes cover HD=64)
    float4 q0 = *(const float4*)&g_q[((size_t)b * NH_ + kv * G_ + 0) * HD_ + l16 * 4];
    float4 q1 = *(const float4*)&g_q[((size_t)b * NH_ + kv * G_ + 1) * HD_ + l16 * 4];
    float4 q2 = *(const float4*)&g_q[((size_t)b * NH_ + kv * G_ + 2) * HD_ + l16 * 4];
    float4 q3 = *(const float4*)&g_q[((size_t)b * NH_ + kv * G_ + 3) * HD_ + l16 * 4];

    const float* knew_p = g_k + ((size_t)b * NKV_ + kv) * HD_;
    const float* vnew_p = g_qkv + (size_t)b * QKVN_ + NH_ * HD_ + NKV_ * HD_ + kv * HD_;
    __syncthreads();

    // ---- pass 1: scores (UNIFORM trip count: shuffles execute warp-wide) ----
    float m0 = -1e30f, m1 = -1e30f, m2 = -1e30f, m3 = -1e30f;
    int sub = w * 2 + half;            // 0..15: position lane-group
    int niter = (ctx + 15) >> 4;       // uniform across ALL threads in block
    for (int i = 0; i < niter; i++) {
        int s = sub + (i << 4);
        bool valid = (s < ctx);
        float4 k4 = make_float4(0.f, 0.f, 0.f, 0.f);
        if (valid) {
            const float* kp;
            if (s == ctx - 1) kp = knew_p;
            else {
                int blk = sbt[s >> 4];
                kp = kc + (((size_t)blk * BS_ + (s & 15)) * NKV_ + kv) * HD_;
            }
            k4 = *(const float4*)&kp[l16 * 4];
        }
        float d0 = q0.x * k4.x + q0.y * k4.y + q0.z * k4.z + q0.w * k4.w;
        float d1 = q1.x * k4.x + q1.y * k4.y + q1.z * k4.z + q1.w * k4.w;
        float d2 = q2.x * k4.x + q2.y * k4.y + q2.z * k4.z + q2.w * k4.w;
        float d3 = q3.x * k4.x + q3.y * k4.y + q3.z * k4.z + q3.w * k4.w;
#pragma unroll
        for (int o = 8; o; o >>= 1) {
            d0 += __shfl_xor_sync(0xffffffffu, d0, o);
            d1 += __shfl_xor_sync(0xffffffffu, d1, o);
            d2 += __shfl_xor_sync(0xffffffffu, d2, o);
            d3 += __shfl_xor_sync(0xffffffffu, d3, o);
        }
        d0 *= SCALE_; d1 *= SCALE_; d2 *= SCALE_; d3 *= SCALE_;
        if (valid) {
            if (l16 == 0) { sc[0][s] = d0; sc[1][s] = d1; sc[2][s] = d2; sc[3][s] = d3; }
            m0 = fmaxf(m0, d0); m1 = fmaxf(m1, d1); m2 = fmaxf(m2, d2); m3 = fmaxf(m3, d3);
        }
    }
    m0 = fmaxf(m0, __shfl_xor_sync(0xffffffffu, m0, 16));
    m1 = fmaxf(m1, __shfl_xor_sync(0xffffffffu, m1, 16));
    m2 = fmaxf(m2, __shfl_xor_sync(0xffffffffu, m2, 16));
    m3 = fmaxf(m3, __shfl_xor_sync(0xffffffffu, m3, 16));
    if (lane == 0) { wmax[w][0] = m0; wmax[w][1] = m1; wmax[w][2] = m2; wmax[w][3] = m3; }
    __syncthreads();
    if (t < G_) {
        float m = wmax[0][t];
#pragma unroll
        for (int ww = 1; ww < 8; ww++) m = fmaxf(m, wmax[ww][t]);
        gmax[t] = m;
    }
    __syncthreads();

    // ---- pass 2a: exp + sum (shuffles AFTER divergent loop: reconverged) ----
#pragma unroll
    for (int g = 0; g < G_; g++) {
        float mg = gmax[g];
        float acc = 0.f;
        for (int s = t; s < ctx; s += 256) {
            float p = __expf(sc[g][s] - mg);
            sc[g][s] = p;
            acc += p;
        }
#pragma unroll
        for (int o = 16; o; o >>= 1) acc += __shfl_xor_sync(0xffffffffu, acc, o);
        if (lane == 0) atomicAdd(&gsum[g], acc);
    }
    __syncthreads();

    // ---- pass 2b: PV (no intra-loop syncs; shuffles after loop) ----
    float4 a0 = {0,0,0,0}, a1 = {0,0,0,0}, a2 = {0,0,0,0}, a3 = {0,0,0,0};
    for (int s = sub; s < ctx; s += 16) {
        const float* vp;
        if (s == ctx - 1) vp = vnew_p;
        else {
            int blk = sbt[s >> 4];
            vp = vc + (((size_t)blk * BS_ + (s & 15)) * NKV_ + kv) * HD_;
        }
        float4 v4 = *(const float4*)&vp[l16 * 4];
        float p0 = sc[0][s], p1 = sc[1][s], p2 = sc[2][s], p3 = sc[3][s];
        a0.x += p0 * v4.x; a0.y += p0 * v4.y; a0.z += p0 * v4.z; a0.w += p0 * v4.w;
        a1.x += p1 * v4.x; a1.y += p1 * v4.y; a1.z += p1 * v4.z; a1.w += p1 * v4.w;
        a2.x += p2 * v4.x; a2.y += p2 * v4.y; a2.z += p2 * v4.z; a2.w += p2 * v4.w;
        a3.x += p3 * v4.x; a3.y += p3 * v4.y; a3.z += p3 * v4.z; a3.w += p3 * v4.w;
    }
    // combine the two 16-lane halves (different position sets, same (g,d) map)
    a0.x += __shfl_xor_sync(0xffffffffu, a0.x, 16); a0.y += __shfl_xor_sync(0xffffffffu, a0.y, 16);
    a0.z += __shfl_xor_sync(0xffffffffu, a0.z, 16); a0.w += __shfl_xor_sync(0xffffffffu, a0.w, 16);
    a1.x += __shfl_xor_sync(0xffffffffu, a1.x, 16); a1.y += __shfl_xor_sync(0xffffffffu, a1.y, 16);
    a1.z += __shfl_xor_sync(0xffffffffu, a1.z, 16); a1.w += __shfl_xor_sync(0xffffffffu, a1.w, 16);
    a2.x += __shfl_xor_sync(0xffffffffu, a2.x, 16); a2.y += __shfl_xor_sync(0xffffffffu, a2.y, 16);
    a2.z += __shfl_xor_sync(0xffffffffu, a2.z, 16); a2.w += __shfl_xor_sync(0xffffffffu, a2.w, 16);
    a3.x += __shfl_xor_sync(0xffffffffu, a3.x, 16); a3.y += __shfl_xor_sync(0xffffffffu, a3.y, 16);
    a3.z += __shfl_xor_sync(0xffffffffu, a3.z, 16); a3.w += __shfl_xor_sync(0xffffffffu, a3.w, 16);
    if (half == 0) {
        *(float4*)&obuf[w][0][l16 * 4] = a0;
        *(float4*)&obuf[w][1][l16 * 4] = a1;
        *(float4*)&obuf[w][2][l16 * 4] = a2;
        *(float4*)&obuf[w][3][l16 * 4] = a3;
    }
    __syncthreads();

    {
        int g = t >> 6, d = t & 63;   // 256 threads = 4 heads x 64 dims
        float acc = 0.f;
#pragma unroll
        for (int ww = 0; ww < 8; ww++) acc += obuf[ww][g][d];
        g_att[(size_t)b * (NH_ * HD_) + (kv * G_ + g) * HD_ + d] = acc / gsum[g];
    }
}

// ---------------- launch: kernel launches ONLY ----------------
extern "C" void kernel_launch(void* const* d_in, const int* in_sizes, int n_in,
                              void* d_out, int out_size)
{
    const float* hidden    = (const float*)d_in[0];
    const int*   positions = (const int*)  d_in[1];
    const int*   ctxlens   = (const int*)  d_in[2];
    // d_in[3] slot_mapping: unused (phys(ctx-1) == slot; handled in attention)
    const int*   btab      = (const int*)  d_in[4];
    const float* kc        = (const float*)d_in[5];
    const float* vc        = (const float*)d_in[6];
    const float* wqkv      = (const float*)d_in[7];
    const float* wout      = (const float*)d_in[8];
    const float* qlw       = (const float*)d_in[9];
    const float* klw       = (const float*)d_in[10];
    float* out = (float*)d_out;

    zero_qkv_kernel<<<(B_ * QKVN_ + 255) / 256, 256>>>();
    zero_out_kernel<<<(B_ * HID_ + 255) / 256, 256>>>(out, B_ * HID_);

    gemm_qkv_kernel<<<dim3(QKVN_ / 64, 4), 256>>>(hidden, wqkv);
    prep_kernel<<<B_, 256>>>(positions, qlw, klw);
    attn_kernel<<<dim3(NKV_, B_), 256>>>(kc, vc, ctxlens, btab);
    gemm_out_kernel<<<dim3(HID_ / 64, 4), 256>>>(wout, out);
}

// round 7
// speedup vs baseline: 1.4517x; 1.4517x over previous
#include <cuda_runtime.h>
#include <cuda_bf16.h>
#include <cstdint>
#include <math.h>

// ---------------- problem constants ----------------
#define B_     64
#define HID_   2048
#define NH_    32
#define NKV_   8
#define HD_    64
#define G_     4          // NH/NKV
#define BS_    16
#define MAXB_  128
#define MAXKV_ 2048
#define QKVN_  3072       // NH*HD + 2*NKV*HD
#define SCALE_ 0.125f     // 64^-0.5
#define T_     64         // attention KV tile

// ---------------- scratch: device globals only ----------------
__device__ float g_qkv [B_ * QKVN_];            // 64x3072 qkv projection
__device__ float g_q   [B_ * NH_ * HD_];        // rmsnorm+rope'd q
__device__ float g_k   [B_ * NKV_ * HD_];       // rmsnorm+rope'd new k
__device__ float g_att [B_ * NH_ * HD_];        // attention output (64x2048)
__device__ float g_part[2359296];               // GEMM split partials
__device__ float g_sc  [B_ * NKV_ * G_ * MAXKV_]; // attention scores (16.8MB, L2-resident)

// ---------------- cp.async helpers ----------------
__device__ __forceinline__ void cpa16(void* smem, const void* gptr) {
    unsigned a = (unsigned)__cvta_generic_to_shared(smem);
    asm volatile("cp.async.cg.shared.global [%0], [%1], 16;\n" :: "r"(a), "l"(gptr));
}
#define CPA_COMMIT() asm volatile("cp.async.commit_group;\n")
#define CPA_WAIT0()  asm volatile("cp.async.wait_group 0;\n")
#define CPA_WAIT1()  asm volatile("cp.async.wait_group 1;\n")

// ============================================================================
// GEMM: part[split] (64xN tile) = A(64xKchunk) * B(KchunkxN)
// BM=64 BN=256 BK=16, 256 threads, 8x8 micro-tile, STG epilogue (no atomics)
// ============================================================================
__device__ __forceinline__ void gemm_body(
    const float* __restrict__ A, const float* __restrict__ B,
    int N, int K, int kb0, int nkb, int split)
{
    __shared__ float As[16][68];    // [k][m] transposed
    __shared__ float Bs[16][256];   // [k][n]

    int n0 = blockIdx.x * 256;
    int t  = threadIdx.x;
    int tx = t & 31, ty = t >> 5;
    int r0 = ty * 8, c0 = tx * 8;

    int a_row = t >> 2, a_c4 = t & 3;

    float acc[8][8];
#pragma unroll
    for (int i = 0; i < 8; i++)
#pragma unroll
        for (int j = 0; j < 8; j++) acc[i][j] = 0.f;

    int kend = kb0 + nkb * 16;
    for (int kb = kb0; kb < kend; kb += 16) {
        float4 av = *(const float4*)&A[(size_t)a_row * K + kb + a_c4 * 4];
        As[a_c4 * 4 + 0][a_row] = av.x;
        As[a_c4 * 4 + 1][a_row] = av.y;
        As[a_c4 * 4 + 2][a_row] = av.z;
        As[a_c4 * 4 + 3][a_row] = av.w;
#pragma unroll
        for (int r = 0; r < 4; r++) {
            int id = t + 256 * r;            // 0..1023
            int row = id >> 6, col4 = id & 63;
            *(float4*)&Bs[row][col4 * 4] =
                *(const float4*)&B[(size_t)(kb + row) * N + n0 + col4 * 4];
        }
        __syncthreads();
#pragma unroll
        for (int kk = 0; kk < 16; kk++) {
            float4 a0 = *(const float4*)&As[kk][r0];
            float4 a1 = *(const float4*)&As[kk][r0 + 4];
            float4 b0 = *(const float4*)&Bs[kk][c0];
            float4 b1 = *(const float4*)&Bs[kk][c0 + 4];
            float am[8] = {a0.x, a0.y, a0.z, a0.w, a1.x, a1.y, a1.z, a1.w};
            float bn[8] = {b0.x, b0.y, b0.z, b0.w, b1.x, b1.y, b1.z, b1.w};
#pragma unroll
            for (int i = 0; i < 8; i++)
#pragma unroll
                for (int j = 0; j < 8; j++) acc[i][j] += am[i] * bn[j];
        }
        __syncthreads();
    }

    float* dst = g_part + (size_t)split * (64 * N);
#pragma unroll
    for (int i = 0; i < 8; i++) {
        float* row = dst + (size_t)(r0 + i) * N + n0 + c0;
        *(float4*)&row[0] = make_float4(acc[i][0], acc[i][1], acc[i][2], acc[i][3]);
        *(float4*)&row[4] = make_float4(acc[i][4], acc[i][5], acc[i][6], acc[i][7]);
    }
}

// QKV: N=3072, K=2048, 12 n-tiles x 12 splits (128 k-tiles: 8x11 + 4x10)
__global__ __launch_bounds__(256) void gemm_qkv_kernel(
    const float* __restrict__ A, const float* __restrict__ B)
{
    int s = blockIdx.y;
    int kb0 = (s * 10 + min(s, 8)) * 16;
    int nkb = 10 + (s < 8 ? 1 : 0);
    gemm_body(A, B, QKVN_, HID_, kb0, nkb, s);
}
// OUT: N=2048, K=2048, 8 n-tiles x 18 splits (128 k-tiles: 2x8 + 16x7)
__global__ __launch_bounds__(256) void gemm_out_kernel(const float* __restrict__ B)
{
    int s = blockIdx.y;
    int kb0 = (s * 7 + min(s, 2)) * 16;
    int nkb = 7 + (s < 2 ? 1 : 0);
    gemm_body(g_att, B, HID_, NH_ * HD_, kb0, nkb, s);
}

// ---------------- split reductions (float4) ----------------
__global__ void reduce_qkv_kernel() {          // 12 x (64*3072)
    int i = blockIdx.x * 256 + threadIdx.x;    // float4 index, n4 = 49152
    const float4* p = (const float4*)g_part;
    float4 s = p[i];
#pragma unroll
    for (int k = 1; k < 12; k++) {
        float4 v = p[(size_t)k * 49152 + i];
        s.x += v.x; s.y += v.y; s.z += v.z; s.w += v.w;
    }
    ((float4*)g_qkv)[i] = s;
}
__global__ void reduce_out_kernel(float* __restrict__ out) {  // 18 x (64*2048)
    int i = blockIdx.x * 256 + threadIdx.x;    // float4 index, n4 = 32768
    const float4* p = (const float4*)g_part;
    float4 s = p[i];
#pragma unroll
    for (int k = 1; k < 18; k++) {
        float4 v = p[(size_t)k * 32768 + i];
        s.x += v.x; s.y += v.y; s.z += v.z; s.w += v.w;
    }
    ((float4*)out)[i] = s;
}

// ---------------- RMSNorm + RoPE ----------------
__global__ __launch_bounds__(256) void prep_kernel(
    const int* __restrict__ positions,
    const float* __restrict__ qw, const float* __restrict__ kw)
{
    int b = blockIdx.x;
    int t = threadIdx.x, w = t >> 5, lane = t & 31;
    __shared__ float cs[32], sn[32];

    int pos = positions[b];
    if (t < 32) {
        // invf = 1e6^(-t/32) via binary exponentiation (pure DMUL chain)
        double v = 1.0;
        if (t & 1)  v *= 0.6493816315762113;    // 1e6^(-1/32)
        if (t & 2)  v *= 0.4216965034285822;    // 1e6^(-2/32)
        if (t & 4)  v *= 0.17782794100389228;   // 1e6^(-4/32)
        if (t & 8)  v *= 0.03162277660168379;   // 1e6^(-8/32)
        if (t & 16) v *= 0.001;                 // 1e6^(-16/32)
        double ang = (double)pos * v;
        double k = floor(ang * 0.15915494309189535);
        float r = (float)(ang - k * 6.283185307179586);
        cs[t] = cosf(r);
        sn[t] = sinf(r);
    }
    __syncthreads();

    const float* row = g_qkv + (size_t)b * QKVN_;
    for (int h = w; h < NH_ + NKV_; h += 8) {
        bool isq = (h < NH_);
        const float* src = isq ? row + h * HD_ : row + NH_ * HD_ + (h - NH_) * HD_;
        float x1 = src[lane], x2 = src[lane + 32];
        float ss = x1 * x1 + x2 * x2;
#pragma unroll
        for (int o = 16; o; o >>= 1) ss += __shfl_xor_sync(0xffffffffu, ss, o);
        float inv = rsqrtf(ss * (1.f / 64.f) + 1e-5f);
        const float* lw = isq ? qw : kw;
        x1 *= inv * lw[lane];
        x2 *= inv * lw[lane + 32];
        float c = cs[lane], s = sn[lane];
        float y1 = x1 * c - x2 * s;
        float y2 = x2 * c + x1 * s;
        float* dst = isq ? g_q + ((size_t)b * NH_ + h) * HD_
                         : g_k + ((size_t)b * NKV_ + (h - NH_)) * HD_;
        dst[lane]      = y1;
        dst[lane + 32] = y2;
    }
}

// ============================================================================
// Paged GQA attention: one CTA per (kv-head, batch). STATIC smem (~36 KB):
// K/V tiles double-buffered; scores live in g_sc (L2-resident global).
// ============================================================================
__device__ __forceinline__ void tile_load(
    float* dst, const float* __restrict__ cache, const float* __restrict__ newrow,
    const int* sbt, int kv, int s0, int ctx, int t)
{
#pragma unroll
    for (int r = 0; r < 4; r++) {
        int id = t + 256 * r;           // 0..1023
        int p = id >> 4, c = id & 15;
        int s = s0 + p;
        if (s < ctx) {
            const float* src;
            if (s == ctx - 1) src = newrow + c * 4;
            else {
                int blk = sbt[s >> 4];
                src = cache + (((size_t)blk * BS_ + (s & 15)) * NKV_ + kv) * HD_ + c * 4;
            }
            cpa16(dst + p * 68 + c * 4, src);
        }
    }
}

__global__ __launch_bounds__(256) void attn_kernel(
    const float* __restrict__ kc, const float* __restrict__ vc,
    const int* __restrict__ ctxlens, const int* __restrict__ btab)
{
    __shared__ float kt[2][T_ * 68];     // 34816 B double-buffered K/V tiles
    __shared__ float qsm[G_ * 68];       // 1088 B
    __shared__ float redm[8];
    __shared__ float gmax[G_], gsum[G_];
    __shared__ int   sbt[MAXB_];

    int kv = blockIdx.x, b = blockIdx.y;
    int t = threadIdx.x, w = t >> 5, lane = t & 31;
    int g = t >> 6, p = t & 63;
    int ctx = ctxlens[b];
    ctx = ctx < 1 ? 1 : (ctx > MAXKV_ ? MAXKV_ : ctx);

    float* sc = g_sc + ((size_t)(b * NKV_ + kv)) * (G_ * MAXKV_);

    if (t < MAXB_) sbt[t] = btab[b * MAXB_ + t];
    if (t < G_)    gsum[t] = 0.f;
    qsm[g * 68 + p] = g_q[((size_t)b * NH_ + kv * G_ + g) * HD_ + p];

    const float* knew_p = g_k + ((size_t)b * NKV_ + kv) * HD_;
    const float* vnew_p = g_qkv + (size_t)b * QKVN_ + NH_ * HD_ + NKV_ * HD_ + kv * HD_;
    __syncthreads();

    int ntiles = (ctx + T_ - 1) / T_;

    // ---- pass 1: scores = q . K (to global sc), double-buffered tiles ----
    float m = -1e30f;
    tile_load(kt[0], kc, knew_p, sbt, kv, 0, ctx, t);
    CPA_COMMIT();
    for (int j = 0; j < ntiles; j++) {
        if (j + 1 < ntiles) {
            tile_load(kt[(j + 1) & 1], kc, knew_p, sbt, kv, (j + 1) * T_, ctx, t);
            CPA_COMMIT();
            CPA_WAIT1();
        } else {
            CPA_WAIT0();
        }
        __syncthreads();
        int s = j * T_ + p;
        if (s < ctx) {
            const float4* kr = (const float4*)(kt[j & 1] + p * 68);
            const float4* qr = (const float4*)(qsm + g * 68);
            float acc = 0.f;
#pragma unroll
            for (int i = 0; i < 16; i++) {
                float4 a = qr[i], k4 = kr[i];
                acc += a.x * k4.x + a.y * k4.y + a.z * k4.z + a.w * k4.w;
            }
            acc *= SCALE_;
            sc[g * MAXKV_ + s] = acc;
            m = fmaxf(m, acc);
        }
        __syncthreads();
    }
#pragma unroll
    for (int o = 16; o; o >>= 1) m = fmaxf(m, __shfl_xor_sync(0xffffffffu, m, o));
    if (lane == 0) redm[w] = m;
    __syncthreads();
    if (t < G_) gmax[t] = fmaxf(redm[2 * t], redm[2 * t + 1]);
    __syncthreads();

    // ---- pass 2: exp + sum (in place, global sc; L2-resident) ----
#pragma unroll
    for (int gg = 0; gg < G_; gg++) {
        float mg = gmax[gg];
        float acc = 0.f;
        for (int s = t; s < ctx; s += 256) {
            float pe = __expf(sc[gg * MAXKV_ + s] - mg);
            sc[gg * MAXKV_ + s] = pe;
            acc += pe;
        }
#pragma unroll
        for (int o = 16; o; o >>= 1) acc += __shfl_xor_sync(0xffffffffu, acc, o);
        if (lane == 0) atomicAdd(&gsum[gg], acc);
    }
    __syncthreads();

    // ---- pass 3: out[g][d] = sum_s p[g][s] * V[s][d], double-buffered ----
    float oacc = 0.f;
    int d = p;   // thread owns (g, d)
    tile_load(kt[0], vc, vnew_p, sbt, kv, 0, ctx, t);
    CPA_COMMIT();
    for (int j = 0; j < ntiles; j++) {
        if (j + 1 < ntiles) {
            tile_load(kt[(j + 1) & 1], vc, vnew_p, sbt, kv, (j + 1) * T_, ctx, t);
            CPA_COMMIT();
            CPA_WAIT1();
        } else {
            CPA_WAIT0();
        }
        __syncthreads();
        int s0 = j * T_;
        int smax = min(T_, ctx - s0);
        const float* vb = kt[j & 1];
        const float4* p4 = (const float4*)(sc + g * MAXKV_ + s0);
        int s4n = smax >> 2;
#pragma unroll 4
        for (int s4 = 0; s4 < s4n; s4++) {
            float4 pv = p4[s4];
            int sb = s4 * 4;
            oacc += pv.x * vb[(sb + 0) * 68 + d];
            oacc += pv.y * vb[(sb + 1) * 68 + d];
            oacc += pv.z * vb[(sb + 2) * 68 + d];
            oacc += pv.w * vb[(sb + 3) * 68 + d];
        }
        for (int s = s4n * 4; s < smax; s++)
            oacc += sc[g * MAXKV_ + s0 + s] * vb[s * 68 + d];
        __syncthreads();
    }
    g_att[(size_t)b * (NH_ * HD_) + (kv * G_ + g) * HD_ + d] = oacc / gsum[g];
}

// ---------------- launch: kernel launches ONLY, no other host APIs ----------
extern "C" void kernel_launch(void* const* d_in, const int* in_sizes, int n_in,
                              void* d_out, int out_size)
{
    const float* hidden    = (const float*)d_in[0];
    const int*   positions = (const int*)  d_in[1];
    const int*   ctxlens   = (const int*)  d_in[2];
    // d_in[3] slot_mapping unused: phys(ctx-1) == slot, new k/v read directly
    const int*   btab      = (const int*)  d_in[4];
    const float* kc        = (const float*)d_in[5];
    const float* vc        = (const float*)d_in[6];
    const float* wqkv      = (const float*)d_in[7];
    const float* wout      = (const float*)d_in[8];
    const float* qlw       = (const float*)d_in[9];
    const float* klw       = (const float*)d_in[10];
    float* out = (float*)d_out;

    gemm_qkv_kernel<<<dim3(12, 12), 256>>>(hidden, wqkv);
    reduce_qkv_kernel<<<192, 256>>>();
    prep_kernel<<<B_, 256>>>(positions, qlw, klw);
    attn_kernel<<<dim3(NKV_, B_), 256>>>(kc, vc, ctxlens, btab);
    gemm_out_kernel<<<dim3(8, 18), 256>>>(wout);
    reduce_out_kernel<<<128, 256>>>(out);
}

// round 8
// speedup vs baseline: 2.0545x; 1.4152x over previous
#include <cuda_runtime.h>
#include <cuda_bf16.h>
#include <cstdint>
#include <math.h>

// ---------------- problem constants ----------------
#define B_     64
#define HID_   2048
#define NH_    32
#define NKV_   8
#define HD_    64
#define G_     4          // NH/NKV
#define BS_    16
#define MAXB_  128
#define MAXKV_ 2048
#define QKVN_  3072       // NH*HD + 2*NKV*HD
#define SCALE_ 0.125f     // 64^-0.5
#define T_     64         // attention KV tile
#define SPLIT_ 4          // KV splits per (b, kv-head)
#define CH_    512        // max chunk = MAXKV_/SPLIT_

// ---------------- scratch: device globals only ----------------
__device__ float g_qkv [B_ * QKVN_];            // 64x3072 qkv projection
__device__ float g_q   [B_ * NH_ * HD_];        // rmsnorm+rope'd q
__device__ float g_k   [B_ * NKV_ * HD_];       // rmsnorm+rope'd new k
__device__ float g_att [B_ * NH_ * HD_];        // attention output (64x2048)
__device__ float g_part[2359296];               // GEMM split partials
__device__ float g_pmax[B_ * NKV_ * SPLIT_ * G_];       // split-KV partial max
__device__ float g_psum[B_ * NKV_ * SPLIT_ * G_];       // split-KV partial sum
__device__ float g_pout[B_ * NKV_ * SPLIT_ * G_ * HD_]; // split-KV partial out (2MB)

// ---------------- cp.async helpers ----------------
__device__ __forceinline__ void cpa16(void* smem, const void* gptr) {
    unsigned a = (unsigned)__cvta_generic_to_shared(smem);
    asm volatile("cp.async.cg.shared.global [%0], [%1], 16;\n" :: "r"(a), "l"(gptr));
}
#define CPA_COMMIT() asm volatile("cp.async.commit_group;\n")
#define CPA_WAIT0()  asm volatile("cp.async.wait_group 0;\n")
#define CPA_WAIT1()  asm volatile("cp.async.wait_group 1;\n")

// ============================================================================
// GEMM: part[split] (64xN tile) = A(64xKchunk) * B(KchunkxN)
// BM=64 BN=256 BK=16, 256 threads, 8x8 micro-tile, STG epilogue (no atomics)
// ============================================================================
__device__ __forceinline__ void gemm_body(
    const float* __restrict__ A, const float* __restrict__ B,
    int N, int K, int kb0, int nkb, int split)
{
    __shared__ float As[16][68];    // [k][m] transposed
    __shared__ float Bs[16][256];   // [k][n]

    int n0 = blockIdx.x * 256;
    int t  = threadIdx.x;
    int tx = t & 31, ty = t >> 5;
    int r0 = ty * 8, c0 = tx * 8;

    int a_row = t >> 2, a_c4 = t & 3;

    float acc[8][8];
#pragma unroll
    for (int i = 0; i < 8; i++)
#pragma unroll
        for (int j = 0; j < 8; j++) acc[i][j] = 0.f;

    int kend = kb0 + nkb * 16;
    for (int kb = kb0; kb < kend; kb += 16) {
        float4 av = *(const float4*)&A[(size_t)a_row * K + kb + a_c4 * 4];
        As[a_c4 * 4 + 0][a_row] = av.x;
        As[a_c4 * 4 + 1][a_row] = av.y;
        As[a_c4 * 4 + 2][a_row] = av.z;
        As[a_c4 * 4 + 3][a_row] = av.w;
#pragma unroll
        for (int r = 0; r < 4; r++) {
            int id = t + 256 * r;            // 0..1023
            int row = id >> 6, col4 = id & 63;
            *(float4*)&Bs[row][col4 * 4] =
                *(const float4*)&B[(size_t)(kb + row) * N + n0 + col4 * 4];
        }
        __syncthreads();
#pragma unroll
        for (int kk = 0; kk < 16; kk++) {
            float4 a0 = *(const float4*)&As[kk][r0];
            float4 a1 = *(const float4*)&As[kk][r0 + 4];
            float4 b0 = *(const float4*)&Bs[kk][c0];
            float4 b1 = *(const float4*)&Bs[kk][c0 + 4];
            float am[8] = {a0.x, a0.y, a0.z, a0.w, a1.x, a1.y, a1.z, a1.w};
            float bn[8] = {b0.x, b0.y, b0.z, b0.w, b1.x, b1.y, b1.z, b1.w};
#pragma unroll
            for (int i = 0; i < 8; i++)
#pragma unroll
                for (int j = 0; j < 8; j++) acc[i][j] += am[i] * bn[j];
        }
        __syncthreads();
    }

    float* dst = g_part + (size_t)split * (64 * N);
#pragma unroll
    for (int i = 0; i < 8; i++) {
        float* row = dst + (size_t)(r0 + i) * N + n0 + c0;
        *(float4*)&row[0] = make_float4(acc[i][0], acc[i][1], acc[i][2], acc[i][3]);
        *(float4*)&row[4] = make_float4(acc[i][4], acc[i][5], acc[i][6], acc[i][7]);
    }
}

// QKV: N=3072, K=2048, 12 n-tiles x 12 splits (128 k-tiles: 8x11 + 4x10)
__global__ __launch_bounds__(256) void gemm_qkv_kernel(
    const float* __restrict__ A, const float* __restrict__ B)
{
    int s = blockIdx.y;
    int kb0 = (s * 10 + min(s, 8)) * 16;
    int nkb = 10 + (s < 8 ? 1 : 0);
    gemm_body(A, B, QKVN_, HID_, kb0, nkb, s);
}
// OUT: N=2048, K=2048, 8 n-tiles x 18 splits (128 k-tiles: 2x8 + 16x7)
__global__ __launch_bounds__(256) void gemm_out_kernel(const float* __restrict__ B)
{
    int s = blockIdx.y;
    int kb0 = (s * 7 + min(s, 2)) * 16;
    int nkb = 7 + (s < 2 ? 1 : 0);
    gemm_body(g_att, B, HID_, NH_ * HD_, kb0, nkb, s);
}

// ---------------- split reductions (float4) ----------------
__global__ void reduce_qkv_kernel() {          // 12 x (64*3072)
    int i = blockIdx.x * 256 + threadIdx.x;    // float4 index, n4 = 49152
    const float4* p = (const float4*)g_part;
    float4 s = p[i];
#pragma unroll
    for (int k = 1; k < 12; k++) {
        float4 v = p[(size_t)k * 49152 + i];
        s.x += v.x; s.y += v.y; s.z += v.z; s.w += v.w;
    }
    ((float4*)g_qkv)[i] = s;
}
__global__ void reduce_out_kernel(float* __restrict__ out) {  // 18 x (64*2048)
    int i = blockIdx.x * 256 + threadIdx.x;    // float4 index, n4 = 32768
    const float4* p = (const float4*)g_part;
    float4 s = p[i];
#pragma unroll
    for (int k = 1; k < 18; k++) {
        float4 v = p[(size_t)k * 32768 + i];
        s.x += v.x; s.y += v.y; s.z += v.z; s.w += v.w;
    }
    ((float4*)out)[i] = s;
}

// ---------------- RMSNorm + RoPE ----------------
__global__ __launch_bounds__(256) void prep_kernel(
    const int* __restrict__ positions,
    const float* __restrict__ qw, const float* __restrict__ kw)
{
    int b = blockIdx.x;
    int t = threadIdx.x, w = t >> 5, lane = t & 31;
    __shared__ float cs[32], sn[32];

    int pos = positions[b];
    if (t < 32) {
        // invf = 1e6^(-t/32) via binary exponentiation (pure DMUL chain)
        double v = 1.0;
        if (t & 1)  v *= 0.6493816315762113;    // 1e6^(-1/32)
        if (t & 2)  v *= 0.4216965034285822;    // 1e6^(-2/32)
        if (t & 4)  v *= 0.17782794100389228;   // 1e6^(-4/32)
        if (t & 8)  v *= 0.03162277660168379;   // 1e6^(-8/32)
        if (t & 16) v *= 0.001;                 // 1e6^(-16/32)
        double ang = (double)pos * v;
        double k = floor(ang * 0.15915494309189535);
        float r = (float)(ang - k * 6.283185307179586);
        cs[t] = cosf(r);
        sn[t] = sinf(r);
    }
    __syncthreads();

    const float* row = g_qkv + (size_t)b * QKVN_;
    for (int h = w; h < NH_ + NKV_; h += 8) {
        bool isq = (h < NH_);
        const float* src = isq ? row + h * HD_ : row + NH_ * HD_ + (h - NH_) * HD_;
        float x1 = src[lane], x2 = src[lane + 32];
        float ss = x1 * x1 + x2 * x2;
#pragma unroll
        for (int o = 16; o; o >>= 1) ss += __shfl_xor_sync(0xffffffffu, ss, o);
        float inv = rsqrtf(ss * (1.f / 64.f) + 1e-5f);
        const float* lw = isq ? qw : kw;
        x1 *= inv * lw[lane];
        x2 *= inv * lw[lane + 32];
        float c = cs[lane], s = sn[lane];
        float y1 = x1 * c - x2 * s;
        float y2 = x2 * c + x1 * s;
        float* dst = isq ? g_q + ((size_t)b * NH_ + h) * HD_
                         : g_k + ((size_t)b * NKV_ + (h - NH_)) * HD_;
        dst[lane]      = y1;
        dst[lane + 32] = y2;
    }
}

// ============================================================================
// Split-KV attention: one CTA per (kv-head, batch, split). Chunk <= 512 pos.
// Chunk scores in smem; K and V each streamed once via double-buffered cp.async.
// Static smem ~44.7 KB.
// ============================================================================
__device__ __forceinline__ void tile_load(
    float* dst, const float* __restrict__ cache, const float* __restrict__ newrow,
    const int* sbt, int kv, int s0, int send, int ctx, int t)
{
#pragma unroll
    for (int r = 0; r < 4; r++) {
        int id = t + 256 * r;           // 0..1023
        int p = id >> 4, c = id & 15;
        int s = s0 + p;
        if (s < send) {
            const float* src;
            if (s == ctx - 1) src = newrow + c * 4;
            else {
                int blk = sbt[s >> 4];
                src = cache + (((size_t)blk * BS_ + (s & 15)) * NKV_ + kv) * HD_ + c * 4;
            }
            cpa16(dst + p * 68 + c * 4, src);
        }
    }
}

__global__ __launch_bounds__(256) void attn_split_kernel(
    const float* __restrict__ kc, const float* __restrict__ vc,
    const int* __restrict__ ctxlens, const int* __restrict__ btab)
{
    __shared__ float kt[2][T_ * 68];     // 34816 B double-buffered K/V tiles
    __shared__ float scs[G_ * CH_];      // 8192 B chunk scores
    __shared__ float qsm[G_ * 68];       // 1088 B
    __shared__ float redm[8];
    __shared__ float gmax[G_], gsum[G_];
    __shared__ int   sbt[MAXB_];

    int kv = blockIdx.x, b = blockIdx.y, sp = blockIdx.z;
    int t = threadIdx.x, w = t >> 5, lane = t & 31;
    int g = t >> 6, p = t & 63;
    int ctx = ctxlens[b];
    ctx = ctx < 1 ? 1 : (ctx > MAXKV_ ? MAXKV_ : ctx);

    int chunk = (ctx + SPLIT_ - 1) / SPLIT_;
    int c0 = sp * chunk;
    int cn = min(chunk, ctx - c0);       // uniform per block
    int pbase = ((b * NKV_ + kv) * SPLIT_ + sp) * G_;

    if (cn <= 0) {                        // empty split: neutral partials
        if (t < G_) { g_pmax[pbase + t] = -1e30f; g_psum[pbase + t] = 0.f; }
        g_pout[(size_t)(pbase + g) * HD_ + p] = 0.f;
        return;
    }

    if (t < MAXB_) sbt[t] = btab[b * MAXB_ + t];
    if (t < G_)    gsum[t] = 0.f;
    qsm[g * 68 + p] = g_q[((size_t)b * NH_ + kv * G_ + g) * HD_ + p];

    const float* knew_p = g_k + ((size_t)b * NKV_ + kv) * HD_;
    const float* vnew_p = g_qkv + (size_t)b * QKVN_ + NH_ * HD_ + NKV_ * HD_ + kv * HD_;
    __syncthreads();

    int send = c0 + cn;
    int ntiles = (cn + T_ - 1) / T_;

    // ---- pass 1: scores -> smem, double-buffered K tiles ----
    float m = -1e30f;
    tile_load(kt[0], kc, knew_p, sbt, kv, c0, send, ctx, t);
    CPA_COMMIT();
    for (int j = 0; j < ntiles; j++) {
        if (j + 1 < ntiles) {
            tile_load(kt[(j + 1) & 1], kc, knew_p, sbt, kv, c0 + (j + 1) * T_, send, ctx, t);
            CPA_COMMIT();
            CPA_WAIT1();
        } else {
            CPA_WAIT0();
        }
        __syncthreads();
        int sl = j * T_ + p;             // local position in chunk
        if (sl < cn) {
            const float4* kr = (const float4*)(kt[j & 1] + p * 68);
            const float4* qr = (const float4*)(qsm + g * 68);
            float acc = 0.f;
#pragma unroll
            for (int i = 0; i < 16; i++) {
                float4 a = qr[i], k4 = kr[i];
                acc += a.x * k4.x + a.y * k4.y + a.z * k4.z + a.w * k4.w;
            }
            acc *= SCALE_;
            scs[g * CH_ + sl] = acc;
            m = fmaxf(m, acc);
        }
        __syncthreads();
    }
    // per-g max: warp reduce (warp covers single g) then pair combine
#pragma unroll
    for (int o = 16; o; o >>= 1) m = fmaxf(m, __shfl_xor_sync(0xffffffffu, m, o));
    if (lane == 0) redm[w] = m;
    __syncthreads();
    if (t < G_) gmax[t] = fmaxf(redm[2 * t], redm[2 * t + 1]);
    __syncthreads();

    // ---- pass 2: exp + sum in smem ----
#pragma unroll
    for (int gg = 0; gg < G_; gg++) {
        float mg = gmax[gg];
        float acc = 0.f;
        for (int s = t; s < cn; s += 256) {
            float pe = __expf(scs[gg * CH_ + s] - mg);
            scs[gg * CH_ + s] = pe;
            acc += pe;
        }
#pragma unroll
        for (int o = 16; o; o >>= 1) acc += __shfl_xor_sync(0xffffffffu, acc, o);
        if (lane == 0) atomicAdd(&gsum[gg], acc);
    }
    __syncthreads();

    // ---- pass 3: partial out[g][d] = sum_s p[s] * V[s][d] ----
    float oacc = 0.f;
    int d = p;
    tile_load(kt[0], vc, vnew_p, sbt, kv, c0, send, ctx, t);
    CPA_COMMIT();
    for (int j = 0; j < ntiles; j++) {
        if (j + 1 < ntiles) {
            tile_load(kt[(j + 1) & 1], vc, vnew_p, sbt, kv, c0 + (j + 1) * T_, send, ctx, t);
            CPA_COMMIT();
            CPA_WAIT1();
        } else {
            CPA_WAIT0();
        }
        __syncthreads();
        int s0 = j * T_;
        int smax = min(T_, cn - s0);
        const float* vb = kt[j & 1];
        const float4* p4 = (const float4*)(scs + g * CH_ + s0);
        int s4n = smax >> 2;
#pragma unroll 4
        for (int s4 = 0; s4 < s4n; s4++) {
            float4 pv = p4[s4];
            int sb = s4 * 4;
            oacc += pv.x * vb[(sb + 0) * 68 + d];
            oacc += pv.y * vb[(sb + 1) * 68 + d];
            oacc += pv.z * vb[(sb + 2) * 68 + d];
            oacc += pv.w * vb[(sb + 3) * 68 + d];
        }
        for (int s = s4n * 4; s < smax; s++)
            oacc += scs[g * CH_ + s0 + s] * vb[s * 68 + d];
        __syncthreads();
    }
    g_pout[(size_t)(pbase + g) * HD_ + d] = oacc;
    if (t < G_) { g_pmax[pbase + t] = gmax[t]; g_psum[pbase + t] = gsum[t]; }
}

// ---------------- combine splits: one CTA per (kv, b) ----------------
__global__ __launch_bounds__(256) void attn_combine_kernel()
{
    int kv = blockIdx.x, b = blockIdx.y;
    int t = threadIdx.x, g = t >> 6, d = t & 63;
    int base = (b * NKV_ + kv) * SPLIT_ * G_;

    float mi[SPLIT_];
    float M = -1e30f;
#pragma unroll
    for (int i = 0; i < SPLIT_; i++) {
        mi[i] = g_pmax[base + i * G_ + g];
        M = fmaxf(M, mi[i]);
    }
    float denom = 0.f, numer = 0.f;
#pragma unroll
    for (int i = 0; i < SPLIT_; i++) {
        float wgt = __expf(mi[i] - M);
        denom += wgt * g_psum[base + i * G_ + g];
        numer += wgt * g_pout[(size_t)(base + i * G_ + g) * HD_ + d];
    }
    g_att[(size_t)b * (NH_ * HD_) + (kv * G_ + g) * HD_ + d] = numer / denom;
}

// ---------------- launch: kernel launches ONLY ----------------
extern "C" void kernel_launch(void* const* d_in, const int* in_sizes, int n_in,
                              void* d_out, int out_size)
{
    const float* hidden    = (const float*)d_in[0];
    const int*   positions = (const int*)  d_in[1];
    const int*   ctxlens   = (const int*)  d_in[2];
    // d_in[3] slot_mapping unused: phys(ctx-1) == slot, new k/v read directly
    const int*   btab      = (const int*)  d_in[4];
    const float* kc        = (const float*)d_in[5];
    const float* vc        = (const float*)d_in[6];
    const float* wqkv      = (const float*)d_in[7];
    const float* wout      = (const float*)d_in[8];
    const float* qlw       = (const float*)d_in[9];
    const float* klw       = (const float*)d_in[10];
    float* out = (float*)d_out;

    gemm_qkv_kernel<<<dim3(12, 12), 256>>>(hidden, wqkv);
    reduce_qkv_kernel<<<192, 256>>>();
    prep_kernel<<<B_, 256>>>(positions, qlw, klw);
    attn_split_kernel<<<dim3(NKV_, B_, SPLIT_), 256>>>(kc, vc, ctxlens, btab);
    attn_combine_kernel<<<dim3(NKV_, B_), 256>>>();
    gemm_out_kernel<<<dim3(8, 18), 256>>>(wout);
    reduce_out_kernel<<<128, 256>>>(out);
}

// round 9
// speedup vs baseline: 2.1915x; 1.0667x over previous
#include <cuda_runtime.h>
#include <cuda_bf16.h>
#include <cstdint>
#include <math.h>

// ---------------- problem constants ----------------
#define B_     64
#define HID_   2048
#define NH_    32
#define NKV_   8
#define HD_    64
#define G_     4          // NH/NKV
#define BS_    16
#define MAXB_  128
#define MAXKV_ 2048
#define QKVN_  3072       // NH*HD + 2*NKV*HD
#define SCALE_ 0.125f     // 64^-0.5
#define T_     64         // attention KV tile
#define SPLIT_ 4          // KV splits per (b, kv-head)
#define CH_    512        // max chunk = MAXKV_/SPLIT_
#define SCP_   520        // scs row stride (floats): 520%32==8 -> conflict-free

// K-tile slot permutation: chunk c stored at column TBL[c]*4 floats.
// Property: (p*17 + TBL[4*qtr+i]) mod 8 distinct over any 8-lane phase.
__device__ __constant__ int TBL_[16] = {0,1,2,3, 10,11,12,13, 4,5,6,7, 14,15,8,9};

// ---------------- scratch: device globals only ----------------
__device__ float g_qkv [B_ * QKVN_];
__device__ float g_q   [B_ * NH_ * HD_];
__device__ float g_k   [B_ * NKV_ * HD_];
__device__ float g_att [B_ * NH_ * HD_];
__device__ float g_part[4718592];               // GEMM split partials (18.9MB)
__device__ float g_pmax[B_ * NKV_ * SPLIT_ * G_];
__device__ float g_psum[B_ * NKV_ * SPLIT_ * G_];
__device__ float g_pout[B_ * NKV_ * SPLIT_ * G_ * HD_];

// ---------------- cp.async helpers ----------------
__device__ __forceinline__ void cpa16(void* smem, const void* gptr) {
    unsigned a = (unsigned)__cvta_generic_to_shared(smem);
    asm volatile("cp.async.cg.shared.global [%0], [%1], 16;\n" :: "r"(a), "l"(gptr));
}
__device__ __forceinline__ void cpa16z(void* smem, const void* gptr, bool v) {
    unsigned a = (unsigned)__cvta_generic_to_shared(smem);
    int sz = v ? 16 : 0;
    asm volatile("cp.async.cg.shared.global [%0], [%1], 16, %2;\n"
                 :: "r"(a), "l"(gptr), "r"(sz));
}
#define CPA_COMMIT() asm volatile("cp.async.commit_group;\n")
#define CPA_WAIT0()  asm volatile("cp.async.wait_group 0;\n")
#define CPA_WAIT1()  asm volatile("cp.async.wait_group 1;\n")

// ============================================================================
// GEMM: part[split] = A(64xKchunk) * B(KchunkxN); BM64 BN256 BK16, 8x8 micro,
// cp.async double-buffered, STG epilogue.
// ============================================================================
__device__ __forceinline__ void gemm_body(
    const float* __restrict__ A, const float* __restrict__ B,
    int N, int K, int kb0, int nkb, int split)
{
    __shared__ float As[2][64 * 16];    // [buf][m*16+k]  8KB
    __shared__ float Bs[2][16][256];    // 32KB

    int n0 = blockIdx.x * 256;
    int t  = threadIdx.x;
    int tx = t & 31, ty = t >> 5;
    int r0 = ty * 8, c0 = tx * 8;
    int a_row = t >> 2, a_c4 = t & 3;

    float acc[8][8];
#pragma unroll
    for (int i = 0; i < 8; i++)
#pragma unroll
        for (int j = 0; j < 8; j++) acc[i][j] = 0.f;

    // prefetch tile 0
    cpa16(&As[0][a_row * 16 + a_c4 * 4], &A[(size_t)a_row * K + kb0 + a_c4 * 4]);
#pragma unroll
    for (int r = 0; r < 4; r++) {
        int id = t + 256 * r, row = id >> 6, col4 = id & 63;
        cpa16(&Bs[0][row][col4 * 4], &B[(size_t)(kb0 + row) * N + n0 + col4 * 4]);
    }
    CPA_COMMIT();

    for (int kt = 0; kt < nkb; kt++) {
        int buf = kt & 1;
        if (kt + 1 < nkb) {
            int kb = kb0 + (kt + 1) * 16, nb = buf ^ 1;
            cpa16(&As[nb][a_row * 16 + a_c4 * 4], &A[(size_t)a_row * K + kb + a_c4 * 4]);
#pragma unroll
            for (int r = 0; r < 4; r++) {
                int id = t + 256 * r, row = id >> 6, col4 = id & 63;
                cpa16(&Bs[nb][row][col4 * 4], &B[(size_t)(kb + row) * N + n0 + col4 * 4]);
            }
            CPA_COMMIT();
            CPA_WAIT1();
        } else {
            CPA_WAIT0();
        }
        __syncthreads();
#pragma unroll
        for (int kk = 0; kk < 16; kk++) {
            float am[8];
#pragma unroll
            for (int i = 0; i < 8; i++) am[i] = As[buf][(r0 + i) * 16 + kk];
            float4 b0 = *(const float4*)&Bs[buf][kk][c0];
            float4 b1 = *(const float4*)&Bs[buf][kk][c0 + 4];
            float bn[8] = {b0.x, b0.y, b0.z, b0.w, b1.x, b1.y, b1.z, b1.w};
#pragma unroll
            for (int i = 0; i < 8; i++)
#pragma unroll
                for (int j = 0; j < 8; j++) acc[i][j] += am[i] * bn[j];
        }
        __syncthreads();
    }

    float* dst = g_part + (size_t)split * (64 * N);
#pragma unroll
    for (int i = 0; i < 8; i++) {
        float* row = dst + (size_t)(r0 + i) * N + n0 + c0;
        *(float4*)&row[0] = make_float4(acc[i][0], acc[i][1], acc[i][2], acc[i][3]);
        *(float4*)&row[4] = make_float4(acc[i][4], acc[i][5], acc[i][6], acc[i][7]);
    }
}

// QKV: N=3072, K=2048, 24 splits (8x6 + 16x5 k-tiles), grid (12,24)
__global__ __launch_bounds__(256) void gemm_qkv_kernel(
    const float* __restrict__ A, const float* __restrict__ B)
{
    int s = blockIdx.y;
    int kb0 = (s * 5 + min(s, 8)) * 16;
    int nkb = 5 + (s < 8 ? 1 : 0);
    gemm_body(A, B, QKVN_, HID_, kb0, nkb, s);
}
// OUT: N=2048, K=2048, 36 splits (20x4 + 16x3), grid (8,36)
__global__ __launch_bounds__(256) void gemm_out_kernel(const float* __restrict__ B)
{
    int s = blockIdx.y;
    int kb0 = (s * 3 + min(s, 20)) * 16;
    int nkb = 3 + (s < 20 ? 1 : 0);
    gemm_body(g_att, B, HID_, NH_ * HD_, kb0, nkb, s);
}

// ---------------- split reductions (float4) ----------------
__global__ void reduce_qkv_kernel() {          // 24 x (64*3072)
    int i = blockIdx.x * 256 + threadIdx.x;    // n4 = 49152
    const float4* p = (const float4*)g_part;
    float4 s = p[i];
#pragma unroll
    for (int k = 1; k < 24; k++) {
        float4 v = p[(size_t)k * 49152 + i];
        s.x += v.x; s.y += v.y; s.z += v.z; s.w += v.w;
    }
    ((float4*)g_qkv)[i] = s;
}
__global__ void reduce_out_kernel(float* __restrict__ out) {  // 36 x (64*2048)
    int i = blockIdx.x * 256 + threadIdx.x;    // n4 = 32768
    const float4* p = (const float4*)g_part;
    float4 s = p[i];
#pragma unroll
    for (int k = 1; k < 36; k++) {
        float4 v = p[(size_t)k * 32768 + i];
        s.x += v.x; s.y += v.y; s.z += v.z; s.w += v.w;
    }
    ((float4*)out)[i] = s;
}

// ---------------- RMSNorm + RoPE ----------------
__global__ __launch_bounds__(256) void prep_kernel(
    const int* __restrict__ positions,
    const float* __restrict__ qw, const float* __restrict__ kw)
{
    int b = blockIdx.x;
    int t = threadIdx.x, w = t >> 5, lane = t & 31;
    __shared__ float cs[32], sn[32];

    int pos = positions[b];
    if (t < 32) {
        double v = 1.0;
        if (t & 1)  v *= 0.6493816315762113;
        if (t & 2)  v *= 0.4216965034285822;
        if (t & 4)  v *= 0.17782794100389228;
        if (t & 8)  v *= 0.03162277660168379;
        if (t & 16) v *= 0.001;
        double ang = (double)pos * v;
        double k = floor(ang * 0.15915494309189535);
        float r = (float)(ang - k * 6.283185307179586);
        cs[t] = cosf(r);
        sn[t] = sinf(r);
    }
    __syncthreads();

    const float* row = g_qkv + (size_t)b * QKVN_;
    for (int h = w; h < NH_ + NKV_; h += 8) {
        bool isq = (h < NH_);
        const float* src = isq ? row + h * HD_ : row + NH_ * HD_ + (h - NH_) * HD_;
        float x1 = src[lane], x2 = src[lane + 32];
        float ss = x1 * x1 + x2 * x2;
#pragma unroll
        for (int o = 16; o; o >>= 1) ss += __shfl_xor_sync(0xffffffffu, ss, o);
        float inv = rsqrtf(ss * (1.f / 64.f) + 1e-5f);
        const float* lw = isq ? qw : kw;
        x1 *= inv * lw[lane];
        x2 *= inv * lw[lane + 32];
        float c = cs[lane], s = sn[lane];
        float y1 = x1 * c - x2 * s;
        float y2 = x2 * c + x1 * s;
        float* dst = isq ? g_q + ((size_t)b * NH_ + h) * HD_
                         : g_k + ((size_t)b * NKV_ + (h - NH_)) * HD_;
        dst[lane]      = y1;
        dst[lane + 32] = y2;
    }
}

// ============================================================================
// Split-KV attention. Pass1: thread=(pos,qtr), K read once, 3-shuffle combine.
// Pass3: thread=(dim,sgroup), V read once, prob broadcasts. Static smem 47.9KB.
// ============================================================================
template<bool SW>
__device__ __forceinline__ void tile_load(
    float* dst, const float* __restrict__ cache, const float* __restrict__ newrow,
    const int* sbt, int kv, int s0, int send, int ctx, int t, int colw)
{
    int c = t & 15;
#pragma unroll
    for (int r = 0; r < 4; r++) {
        int p = (t >> 4) + 16 * r;
        int s = s0 + p;
        bool v = (s < send);
        const float* src = cache;
        if (v) {
            if (s == ctx - 1) src = newrow + c * 4;
            else {
                int blk = sbt[s >> 4];
                src = cache + (((size_t)blk * BS_ + (s & 15)) * NKV_ + kv) * HD_ + c * 4;
            }
        }
        int col = SW ? colw : c * 4;
        cpa16z(dst + p * 68 + col, src, v);
    }
}

__global__ __launch_bounds__(256) void attn_split_kernel(
    const float* __restrict__ kc, const float* __restrict__ vc,
    const int* __restrict__ ctxlens, const int* __restrict__ btab)
{
    __shared__ float kt[2][T_ * 68];      // 34816 B
    __shared__ float scs[G_ * SCP_];      // 8320 B
    __shared__ float aux[1024];           // 4096 B: qsm (pass1) / obuf (epilogue)
    __shared__ float redm[8][4];
    __shared__ float gmax[G_], gsum[G_];
    __shared__ int   sbt[MAXB_];

    int kv = blockIdx.x, b = blockIdx.y, sp = blockIdx.z;
    int t = threadIdx.x, w = t >> 5, lane = t & 31;
    int ctx = ctxlens[b];
    ctx = ctx < 1 ? 1 : (ctx > MAXKV_ ? MAXKV_ : ctx);

    int chunk = (ctx + SPLIT_ - 1) / SPLIT_;
    int c0 = sp * chunk;
    int cn = min(chunk, ctx - c0);
    int pbase = ((b * NKV_ + kv) * SPLIT_ + sp) * G_;

    if (cn <= 0) {
        if (t < G_) { g_pmax[pbase + t] = -1e30f; g_psum[pbase + t] = 0.f; }
        g_pout[(size_t)(pbase + (t >> 6)) * HD_ + (t & 63)] = 0.f;
        return;
    }

    int colw = TBL_[t & 15] * 4;   // writer slot for tile_load<true>

    if (t < MAXB_) sbt[t] = btab[b * MAXB_ + t];
    if (t < G_)    gsum[t] = 0.f;
    {   // q -> aux, swizzled with TBL (row stride 68)
        int gq = t >> 6, pp = t & 63;
        int col = TBL_[pp >> 2] * 4 + (pp & 3);
        aux[gq * 68 + col] = g_q[((size_t)b * NH_ + kv * G_ + gq) * HD_ + pp];
    }

    const float* knew_p = g_k + ((size_t)b * NKV_ + kv) * HD_;
    const float* vnew_p = g_qkv + (size_t)b * QKVN_ + NH_ * HD_ + NKV_ * HD_ + kv * HD_;
    __syncthreads();

    int send = c0 + cn;
    int ntiles = (cn + T_ - 1) / T_;

    // ---- pass 1: thread = (p, qtr): K fragment once, 4 head-dots, shuffle ----
    int p = t >> 2, qtr = t & 3;
    int o0 = TBL_[qtr * 4 + 0] * 4, o1 = TBL_[qtr * 4 + 1] * 4;
    int o2 = TBL_[qtr * 4 + 2] * 4, o3 = TBL_[qtr * 4 + 3] * 4;
    float m_loc = -1e30f;

    tile_load<true>(kt[0], kc, knew_p, sbt, kv, c0, send, ctx, t, colw);
    CPA_COMMIT();
    for (int j = 0; j < ntiles; j++) {
        if (j + 1 < ntiles) {
            tile_load<true>(kt[(j + 1) & 1], kc, knew_p, sbt, kv,
                            c0 + (j + 1) * T_, send, ctx, t, colw);
            CPA_COMMIT();
            CPA_WAIT1();
        } else {
            CPA_WAIT0();
        }
        __syncthreads();
        const float* kb = kt[j & 1] + p * 68;
        float4 k0 = *(const float4*)(kb + o0);
        float4 k1 = *(const float4*)(kb + o1);
        float4 k2 = *(const float4*)(kb + o2);
        float4 k3 = *(const float4*)(kb + o3);
        float dots[4];
#pragma unroll
        for (int g = 0; g < 4; g++) {
            const float* qb = aux + g * 68;
            float4 qa = *(const float4*)(qb + o0);
            float4 qb4 = *(const float4*)(qb + o1);
            float4 qc = *(const float4*)(qb + o2);
            float4 qd = *(const float4*)(qb + o3);
            dots[g] = qa.x * k0.x + qa.y * k0.y + qa.z * k0.z + qa.w * k0.w
                    + qb4.x * k1.x + qb4.y * k1.y + qb4.z * k1.z + qb4.w * k1.w
                    + qc.x * k2.x + qc.y * k2.y + qc.z * k2.z + qc.w * k2.w
                    + qd.x * k3.x + qd.y * k3.y + qd.z * k3.z + qd.w * k3.w;
        }
        // combine quarters: 3 shuffles; lane qtr ends with full dot for g=qtr
        float sel1 = (qtr & 1) ? dots[0] : dots[1];
        float r1 = __shfl_xor_sync(0xffffffffu, sel1, 1);
        if (qtr & 1) dots[1] += r1; else dots[0] += r1;
        float sel2 = (qtr & 1) ? dots[2] : dots[3];
        float r2 = __shfl_xor_sync(0xffffffffu, sel2, 1);
        if (qtr & 1) dots[3] += r2; else dots[2] += r2;
        int glo = qtr & 1;
        float sel3 = (qtr & 2) ? dots[glo] : dots[2 + glo];
        float r3 = __shfl_xor_sync(0xffffffffu, sel3, 2);
        float fin = ((qtr & 2) ? dots[2 + glo] : dots[glo]) + r3;
        fin *= SCALE_;
        int sl = j * T_ + p;
        if (sl >= cn) fin = -1e30f;
        scs[qtr * SCP_ + sl] = fin;
        m_loc = fmaxf(m_loc, fin);
        __syncthreads();
    }
    // per-g max: reduce over lanes with same qtr, then across warps
    m_loc = fmaxf(m_loc, __shfl_xor_sync(0xffffffffu, m_loc, 4));
    m_loc = fmaxf(m_loc, __shfl_xor_sync(0xffffffffu, m_loc, 8));
    m_loc = fmaxf(m_loc, __shfl_xor_sync(0xffffffffu, m_loc, 16));
    if (lane < 4) redm[w][lane] = m_loc;     // lane == qtr for lanes 0-3
    __syncthreads();
    if (t < G_) {
        float mm = redm[0][t];
#pragma unroll
        for (int ww = 1; ww < 8; ww++) mm = fmaxf(mm, redm[ww][t]);
        gmax[t] = mm;
    }
    __syncthreads();

    // ---- pass 2: exp + sum over padded range (tail scores are -1e30 -> 0) ----
    int cnp = ntiles * T_;
#pragma unroll
    for (int gg = 0; gg < G_; gg++) {
        float mg = gmax[gg];
        float acc = 0.f;
        for (int s = t; s < cnp; s += 256) {
            float pe = __expf(scs[gg * SCP_ + s] - mg);
            scs[gg * SCP_ + s] = pe;
            acc += pe;
        }
#pragma unroll
        for (int o = 16; o; o >>= 1) acc += __shfl_xor_sync(0xffffffffu, acc, o);
        if (lane == 0) atomicAdd(&gsum[gg], acc);
    }
    __syncthreads();

    // ---- pass 3: thread = (d, sg): V once; probs broadcast; V tail zeroed ----
    int d = t & 63, sg = t >> 6;
    float oa0 = 0.f, oa1 = 0.f, oa2 = 0.f, oa3 = 0.f;
    tile_load<false>(kt[0], vc, vnew_p, sbt, kv, c0, send, ctx, t, colw);
    CPA_COMMIT();
    for (int j = 0; j < ntiles; j++) {
        if (j + 1 < ntiles) {
            tile_load<false>(kt[(j + 1) & 1], vc, vnew_p, sbt, kv,
                             c0 + (j + 1) * T_, send, ctx, t, colw);
            CPA_COMMIT();
            CPA_WAIT1();
        } else {
            CPA_WAIT0();
        }
        __syncthreads();
        const float* vb = kt[j & 1];
        const float4* s4 = (const float4*)scs;   // stride SCP_/4 = 130 per g
        int f0 = j * 16 + sg * 4;
#pragma unroll
        for (int i = 0; i < 4; i++) {
            float4 pa = s4[0 * 130 + f0 + i];
            float4 pb = s4[1 * 130 + f0 + i];
            float4 pc = s4[2 * 130 + f0 + i];
            float4 pd = s4[3 * 130 + f0 + i];
            int sb = (sg * 16 + i * 4) * 68 + d;
            float v0 = vb[sb], v1 = vb[sb + 68], v2 = vb[sb + 136], v3 = vb[sb + 204];
            oa0 += pa.x * v0 + pa.y * v1 + pa.z * v2 + pa.w * v3;
            oa1 += pb.x * v0 + pb.y * v1 + pb.z * v2 + pb.w * v3;
            oa2 += pc.x * v0 + pc.y * v1 + pc.z * v2 + pc.w * v3;
            oa3 += pd.x * v0 + pd.y * v1 + pd.z * v2 + pd.w * v3;
        }
        __syncthreads();
    }
    // reduce partial outputs over 4 s-groups via aux (qsm no longer needed)
    aux[sg * 256 + 0 * 64 + d] = oa0;
    aux[sg * 256 + 1 * 64 + d] = oa1;
    aux[sg * 256 + 2 * 64 + d] = oa2;
    aux[sg * 256 + 3 * 64 + d] = oa3;
    __syncthreads();
    {
        int g2 = t >> 6, d2 = t & 63;
        float oo = aux[0 * 256 + g2 * 64 + d2] + aux[1 * 256 + g2 * 64 + d2]
                 + aux[2 * 256 + g2 * 64 + d2] + aux[3 * 256 + g2 * 64 + d2];
        g_pout[(size_t)(pbase + g2) * HD_ + d2] = oo;
    }
    if (t < G_) { g_pmax[pbase + t] = gmax[t]; g_psum[pbase + t] = gsum[t]; }
}

// ---------------- combine splits: one CTA per (kv, b) ----------------
__global__ __launch_bounds__(256) void attn_combine_kernel()
{
    int kv = blockIdx.x, b = blockIdx.y;
    int t = threadIdx.x, g = t >> 6, d = t & 63;
    int base = (b * NKV_ + kv) * SPLIT_ * G_;

    float mi[SPLIT_];
    float M = -1e30f;
#pragma unroll
    for (int i = 0; i < SPLIT_; i++) {
        mi[i] = g_pmax[base + i * G_ + g];
        M = fmaxf(M, mi[i]);
    }
    float denom = 0.f, numer = 0.f;
#pragma unroll
    for (int i = 0; i < SPLIT_; i++) {
        float wgt = __expf(mi[i] - M);
        denom += wgt * g_psum[base + i * G_ + g];
        numer += wgt * g_pout[(size_t)(base + i * G_ + g) * HD_ + d];
    }
    g_att[(size_t)b * (NH_ * HD_) + (kv * G_ + g) * HD_ + d] = numer / denom;
}

// ---------------- launch: kernel launches ONLY ----------------
extern "C" void kernel_launch(void* const* d_in, const int* in_sizes, int n_in,
                              void* d_out, int out_size)
{
    const float* hidden    = (const float*)d_in[0];
    const int*   positions = (const int*)  d_in[1];
    const int*   ctxlens   = (const int*)  d_in[2];
    // d_in[3] slot_mapping unused: phys(ctx-1) == slot, new k/v read directly
    const int*   btab      = (const int*)  d_in[4];
    const float* kc        = (const float*)d_in[5];
    const float* vc        = (const float*)d_in[6];
    const float* wqkv      = (const float*)d_in[7];
    const float* wout      = (const float*)d_in[8];
    const float* qlw       = (const float*)d_in[9];
    const float* klw       = (const float*)d_in[10];
    float* out = (float*)d_out;

    gemm_qkv_kernel<<<dim3(12, 24), 256>>>(hidden, wqkv);
    reduce_qkv_kernel<<<192, 256>>>();
    prep_kernel<<<B_, 256>>>(positions, qlw, klw);
    attn_split_kernel<<<dim3(NKV_, B_, SPLIT_), 256>>>(kc, vc, ctxlens, btab);
    attn_combine_kernel<<<dim3(NKV_, B_), 256>>>();
    gemm_out_kernel<<<dim3(8, 36), 256>>>(wout);
    reduce_out_kernel<<<128, 256>>>(out);
}

// round 10
// speedup vs baseline: 2.2266x; 1.0160x over previous
#include <cuda_runtime.h>
#include <cuda_bf16.h>
#include <cstdint>
#include <math.h>

// ---------------- problem constants ----------------
#define B_     64
#define HID_   2048
#define NH_    32
#define NKV_   8
#define HD_    64
#define G_     4          // NH/NKV
#define BS_    16
#define MAXB_  128
#define MAXKV_ 2048
#define QKVN_  3072       // NH*HD + 2*NKV*HD
#define SCALE_ 0.125f     // 64^-0.5
#define T_     32         // attention KV tile (positions)
#define NBUF_  4          // cp.async pipeline depth
#define SPLIT_ 8          // KV splits per (b, kv-head)
#define CHMAX_ 256        // max chunk = MAXKV_/SPLIT_
#define SCP_   264        // scs row stride (floats), 264%32==8 -> conflict-free

// ---------------- scratch: device globals only ----------------
__device__ float g_qkv [B_ * QKVN_];
__device__ float g_q   [B_ * NH_ * HD_];
__device__ float g_k   [B_ * NKV_ * HD_];
__device__ float g_att [B_ * NH_ * HD_];
__device__ float g_part[4718592];               // GEMM split partials (18.9MB)
__device__ float g_pmax[B_ * NKV_ * SPLIT_ * G_];
__device__ float g_psum[B_ * NKV_ * SPLIT_ * G_];
__device__ float g_pout[B_ * NKV_ * SPLIT_ * G_ * HD_];

// ---------------- cp.async helpers ----------------
__device__ __forceinline__ void cpa16(void* smem, const void* gptr) {
    unsigned a = (unsigned)__cvta_generic_to_shared(smem);
    asm volatile("cp.async.cg.shared.global [%0], [%1], 16;\n" :: "r"(a), "l"(gptr));
}
__device__ __forceinline__ void cpa16z(void* smem, const void* gptr, bool v) {
    unsigned a = (unsigned)__cvta_generic_to_shared(smem);
    int sz = v ? 16 : 0;
    asm volatile("cp.async.cg.shared.global [%0], [%1], 16, %2;\n"
                 :: "r"(a), "l"(gptr), "r"(sz));
}
#define CPA_COMMIT() asm volatile("cp.async.commit_group;\n")
#define CPA_WAIT0()  asm volatile("cp.async.wait_group 0;\n")
#define CPA_WAIT1()  asm volatile("cp.async.wait_group 1;\n")
#define CPA_WAIT3()  asm volatile("cp.async.wait_group 3;\n")

// ============================================================================
// GEMM: part[split] = A(64xKchunk) * B(KchunkxN); BM64 BN256 BK16, 8x8 micro,
// cp.async double-buffered, STG epilogue.
// ============================================================================
__device__ __forceinline__ void gemm_body(
    const float* __restrict__ A, const float* __restrict__ B,
    int N, int K, int kb0, int nkb, int split)
{
    __shared__ float As[2][64 * 16];
    __shared__ float Bs[2][16][256];

    int n0 = blockIdx.x * 256;
    int t  = threadIdx.x;
    int tx = t & 31, ty = t >> 5;
    int r0 = ty * 8, c0 = tx * 8;
    int a_row = t >> 2, a_c4 = t & 3;

    float acc[8][8];
#pragma unroll
    for (int i = 0; i < 8; i++)
#pragma unroll
        for (int j = 0; j < 8; j++) acc[i][j] = 0.f;

    cpa16(&As[0][a_row * 16 + a_c4 * 4], &A[(size_t)a_row * K + kb0 + a_c4 * 4]);
#pragma unroll
    for (int r = 0; r < 4; r++) {
        int id = t + 256 * r, row = id >> 6, col4 = id & 63;
        cpa16(&Bs[0][row][col4 * 4], &B[(size_t)(kb0 + row) * N + n0 + col4 * 4]);
    }
    CPA_COMMIT();

    for (int kt = 0; kt < nkb; kt++) {
        int buf = kt & 1;
        if (kt + 1 < nkb) {
            int kb = kb0 + (kt + 1) * 16, nb = buf ^ 1;
            cpa16(&As[nb][a_row * 16 + a_c4 * 4], &A[(size_t)a_row * K + kb + a_c4 * 4]);
#pragma unroll
            for (int r = 0; r < 4; r++) {
                int id = t + 256 * r, row = id >> 6, col4 = id & 63;
                cpa16(&Bs[nb][row][col4 * 4], &B[(size_t)(kb + row) * N + n0 + col4 * 4]);
            }
            CPA_COMMIT();
            CPA_WAIT1();
        } else {
            CPA_WAIT0();
        }
        __syncthreads();
#pragma unroll
        for (int kk = 0; kk < 16; kk++) {
            float am[8];
#pragma unroll
            for (int i = 0; i < 8; i++) am[i] = As[buf][(r0 + i) * 16 + kk];
            float4 b0 = *(const float4*)&Bs[buf][kk][c0];
            float4 b1 = *(const float4*)&Bs[buf][kk][c0 + 4];
            float bn[8] = {b0.x, b0.y, b0.z, b0.w, b1.x, b1.y, b1.z, b1.w};
#pragma unroll
            for (int i = 0; i < 8; i++)
#pragma unroll
                for (int j = 0; j < 8; j++) acc[i][j] += am[i] * bn[j];
        }
        __syncthreads();
    }

    float* dst = g_part + (size_t)split * (64 * N);
#pragma unroll
    for (int i = 0; i < 8; i++) {
        float* row = dst + (size_t)(r0 + i) * N + n0 + c0;
        *(float4*)&row[0] = make_float4(acc[i][0], acc[i][1], acc[i][2], acc[i][3]);
        *(float4*)&row[4] = make_float4(acc[i][4], acc[i][5], acc[i][6], acc[i][7]);
    }
}

__global__ __launch_bounds__(256) void gemm_qkv_kernel(
    const float* __restrict__ A, const float* __restrict__ B)
{
    int s = blockIdx.y;
    int kb0 = (s * 5 + min(s, 8)) * 16;
    int nkb = 5 + (s < 8 ? 1 : 0);
    gemm_body(A, B, QKVN_, HID_, kb0, nkb, s);
}
__global__ __launch_bounds__(256) void gemm_out_kernel(const float* __restrict__ B)
{
    int s = blockIdx.y;
    int kb0 = (s * 3 + min(s, 20)) * 16;
    int nkb = 3 + (s < 20 ? 1 : 0);
    gemm_body(g_att, B, HID_, NH_ * HD_, kb0, nkb, s);
}

// ---------------- split reductions (float4) ----------------
__global__ void reduce_qkv_kernel() {
    int i = blockIdx.x * 256 + threadIdx.x;    // n4 = 49152
    const float4* p = (const float4*)g_part;
    float4 s = p[i];
#pragma unroll
    for (int k = 1; k < 24; k++) {
        float4 v = p[(size_t)k * 49152 + i];
        s.x += v.x; s.y += v.y; s.z += v.z; s.w += v.w;
    }
    ((float4*)g_qkv)[i] = s;
}
__global__ void reduce_out_kernel(float* __restrict__ out) {
    int i = blockIdx.x * 256 + threadIdx.x;    // n4 = 32768
    const float4* p = (const float4*)g_part;
    float4 s = p[i];
#pragma unroll
    for (int k = 1; k < 36; k++) {
        float4 v = p[(size_t)k * 32768 + i];
        s.x += v.x; s.y += v.y; s.z += v.z; s.w += v.w;
    }
    ((float4*)out)[i] = s;
}

// ---------------- RMSNorm + RoPE ----------------
__global__ __launch_bounds__(256) void prep_kernel(
    const int* __restrict__ positions,
    const float* __restrict__ qw, const float* __restrict__ kw)
{
    int b = blockIdx.x;
    int t = threadIdx.x, w = t >> 5, lane = t & 31;
    __shared__ float cs[32], sn[32];

    int pos = positions[b];
    if (t < 32) {
        double v = 1.0;
        if (t & 1)  v *= 0.6493816315762113;
        if (t & 2)  v *= 0.4216965034285822;
        if (t & 4)  v *= 0.17782794100389228;
        if (t & 8)  v *= 0.03162277660168379;
        if (t & 16) v *= 0.001;
        double ang = (double)pos * v;
        double k = floor(ang * 0.15915494309189535);
        float r = (float)(ang - k * 6.283185307179586);
        cs[t] = cosf(r);
        sn[t] = sinf(r);
    }
    __syncthreads();

    const float* row = g_qkv + (size_t)b * QKVN_;
    for (int h = w; h < NH_ + NKV_; h += 8) {
        bool isq = (h < NH_);
        const float* src = isq ? row + h * HD_ : row + NH_ * HD_ + (h - NH_) * HD_;
        float x1 = src[lane], x2 = src[lane + 32];
        float ss = x1 * x1 + x2 * x2;
#pragma unroll
        for (int o = 16; o; o >>= 1) ss += __shfl_xor_sync(0xffffffffu, ss, o);
        float inv = rsqrtf(ss * (1.f / 64.f) + 1e-5f);
        const float* lw = isq ? qw : kw;
        x1 *= inv * lw[lane];
        x2 *= inv * lw[lane + 32];
        float c = cs[lane], s = sn[lane];
        float y1 = x1 * c - x2 * s;
        float y2 = x2 * c + x1 * s;
        float* dst = isq ? g_q + ((size_t)b * NH_ + h) * HD_
                         : g_k + ((size_t)b * NKV_ + (h - NH_)) * HD_;
        dst[lane]      = y1;
        dst[lane + 32] = y2;
    }
}

// ============================================================================
// Split-KV attention: T=32 tiles, 4-deep cp.async pipeline, SPLIT=8.
// Pass1: thread=(pos, oct); K frag (2 float4: cols oct, oct+8) read once;
// 4-shuffle butterfly -> per-head dots. Conflict-free (fi%8 distinct / phase).
// Pass3: thread=(dim, sgroup); V once; probs float4 broadcasts.
// Static smem ~44 KB.
// ============================================================================
__device__ __forceinline__ void tile_load(
    float* dst, const float* __restrict__ cache, const float* __restrict__ newrow,
    const int* sbt, int kv, int s0, int send, int ctx, int t)
{
    int c = t & 15;
#pragma unroll
    for (int r = 0; r < 2; r++) {
        int p = (t >> 4) + 16 * r;
        int s = s0 + p;
        bool v = (s < send);
        const float* src = cache;
        if (v) {
            if (s == ctx - 1) src = newrow + c * 4;
            else {
                int blk = sbt[s >> 4];
                src = cache + (((size_t)blk * BS_ + (s & 15)) * NKV_ + kv) * HD_ + c * 4;
            }
        }
        cpa16z(dst + p * 68 + c * 4, src, v);
    }
}

__global__ __launch_bounds__(256) void attn_split_kernel(
    const float* __restrict__ kc, const float* __restrict__ vc,
    const int* __restrict__ ctxlens, const int* __restrict__ btab)
{
    __shared__ float kt[NBUF_][T_ * 68];   // 34816 B
    __shared__ float scs[G_ * SCP_];       // 4224 B
    __shared__ float aux[1024];            // 4096 B: q (pass1) / obuf (epilogue)
    __shared__ float redm[8][4];
    __shared__ float gmax[G_], gsum[G_];
    __shared__ int   sbt[MAXB_];

    int kv = blockIdx.x, b = blockIdx.y, sp = blockIdx.z;
    int t = threadIdx.x, w = t >> 5, lane = t & 31;
    int ctx = ctxlens[b];
    ctx = ctx < 1 ? 1 : (ctx > MAXKV_ ? MAXKV_ : ctx);

    int chunk = (ctx + SPLIT_ - 1) / SPLIT_;
    int c0 = sp * chunk;
    int cn = min(chunk, ctx - c0);
    int pbase = ((b * NKV_ + kv) * SPLIT_ + sp) * G_;

    if (cn <= 0) {
        if (t < G_) { g_pmax[pbase + t] = -1e30f; g_psum[pbase + t] = 0.f; }
        g_pout[(size_t)(pbase + (t >> 6)) * HD_ + (t & 63)] = 0.f;
        return;
    }

    if (t < MAXB_) sbt[t] = btab[b * MAXB_ + t];
    if (t < G_)    gsum[t] = 0.f;
    {   // q -> aux rows of 68 floats (straight layout)
        int gq = t >> 6, pp = t & 63;
        aux[gq * 68 + pp] = g_q[((size_t)b * NH_ + kv * G_ + gq) * HD_ + pp];
    }

    const float* knew_p = g_k + ((size_t)b * NKV_ + kv) * HD_;
    const float* vnew_p = g_qkv + (size_t)b * QKVN_ + NH_ * HD_ + NKV_ * HD_ + kv * HD_;
    __syncthreads();

    int send = c0 + cn;
    int ntiles = (cn + T_ - 1) / T_;

    // ---- pass 1: scores ----
    int p = t >> 3, oct = t & 7;
    int g = (oct & 1) * 2 + ((oct >> 1) & 1);   // butterfly ownership
    float m_loc = -1e30f;

#pragma unroll
    for (int i = 0; i < 3; i++) {
        if (i < ntiles) tile_load(kt[i], kc, knew_p, sbt, kv, c0 + i * T_, send, ctx, t);
        CPA_COMMIT();
    }
    for (int j = 0; j < ntiles; j++) {
        if (j + 3 < ntiles)
            tile_load(kt[(j + 3) & 3], kc, knew_p, sbt, kv, c0 + (j + 3) * T_, send, ctx, t);
        CPA_COMMIT();
        CPA_WAIT3();
        __syncthreads();
        const float* kb = kt[j & 3] + p * 68;
        float4 kA = *(const float4*)(kb + oct * 4);
        float4 kB = *(const float4*)(kb + (oct + 8) * 4);
        float dots[4];
#pragma unroll
        for (int gg = 0; gg < 4; gg++) {
            const float* qb = aux + gg * 68;
            float4 qA = *(const float4*)(qb + oct * 4);
            float4 qB = *(const float4*)(qb + (oct + 8) * 4);
            dots[gg] = qA.x * kA.x + qA.y * kA.y + qA.z * kA.z + qA.w * kA.w
                     + qB.x * kB.x + qB.y * kB.y + qB.z * kB.z + qB.w * kB.w;
        }
        // butterfly: L1 (xor1) split by bit0, L2 (xor2) by bit1, L3 (xor4) dup
        bool b0 = oct & 1, b1 = oct & 2;
        float s1 = b0 ? dots[0] : dots[2];
        float r1 = __shfl_xor_sync(0xffffffffu, s1, 1);
        if (!b0) dots[0] += r1; else dots[2] += r1;
        float s2 = b0 ? dots[1] : dots[3];
        float r2 = __shfl_xor_sync(0xffffffffu, s2, 1);
        if (!b0) dots[1] += r2; else dots[3] += r2;
        float v0 = b0 ? dots[2] : dots[0];
        float v1 = b0 ? dots[3] : dots[1];
        float s3 = b1 ? v0 : v1;
        float r3 = __shfl_xor_sync(0xffffffffu, s3, 2);
        float v = (b1 ? v1 : v0) + r3;
        v += __shfl_xor_sync(0xffffffffu, v, 4);
        float fin = v * SCALE_;
        int sl = j * T_ + p;
        if (sl >= cn) fin = -1e30f;
        if (oct < 4) scs[g * SCP_ + sl] = fin;
        m_loc = fmaxf(m_loc, fin);
        __syncthreads();
    }
    // per-g max: reduce over positions (lane bits 3,4), then cross-warp
    m_loc = fmaxf(m_loc, __shfl_xor_sync(0xffffffffu, m_loc, 8));
    m_loc = fmaxf(m_loc, __shfl_xor_sync(0xffffffffu, m_loc, 16));
    if (lane < 4) redm[w][g] = m_loc;
    __syncthreads();
    if (t < G_) {
        float mm = redm[0][t];
#pragma unroll
        for (int ww = 1; ww < 8; ww++) mm = fmaxf(mm, redm[ww][t]);
        gmax[t] = mm;
    }
    __syncthreads();

    // ---- pass 2: exp + sum over padded range ----
    int cnp = ntiles * T_;
#pragma unroll
    for (int gg = 0; gg < G_; gg++) {
        float mg = gmax[gg];
        float acc = 0.f;
        for (int s = t; s < cnp; s += 256) {
            float pe = __expf(scs[gg * SCP_ + s] - mg);
            scs[gg * SCP_ + s] = pe;
            acc += pe;
        }
#pragma unroll
        for (int o = 16; o; o >>= 1) acc += __shfl_xor_sync(0xffffffffu, acc, o);
        if (lane == 0) atomicAdd(&gsum[gg], acc);
    }
    __syncthreads();

    // ---- pass 3: out[g][d] = sum_s p[g][s] * V[s][d] ----
    int d = t & 63, sg = t >> 6;
    float oa0 = 0.f, oa1 = 0.f, oa2 = 0.f, oa3 = 0.f;
#pragma unroll
    for (int i = 0; i < 3; i++) {
        if (i < ntiles) tile_load(kt[i], vc, vnew_p, sbt, kv, c0 + i * T_, send, ctx, t);
        CPA_COMMIT();
    }
    for (int j = 0; j < ntiles; j++) {
        if (j + 3 < ntiles)
            tile_load(kt[(j + 3) & 3], vc, vnew_p, sbt, kv, c0 + (j + 3) * T_, send, ctx, t);
        CPA_COMMIT();
        CPA_WAIT3();
        __syncthreads();
        const float* vb = kt[j & 3];
        const float4* s4 = (const float4*)scs;   // row stride SCP_/4 = 66 per g
        int f0 = j * 8 + sg * 2;
#pragma unroll
        for (int i = 0; i < 2; i++) {
            float4 pa = s4[0 * 66 + f0 + i];
            float4 pb = s4[1 * 66 + f0 + i];
            float4 pc = s4[2 * 66 + f0 + i];
            float4 pd = s4[3 * 66 + f0 + i];
            int sb = (sg * 8 + i * 4) * 68 + d;
            float w0 = vb[sb], w1 = vb[sb + 68], w2 = vb[sb + 136], w3 = vb[sb + 204];
            oa0 += pa.x * w0 + pa.y * w1 + pa.z * w2 + pa.w * w3;
            oa1 += pb.x * w0 + pb.y * w1 + pb.z * w2 + pb.w * w3;
            oa2 += pc.x * w0 + pc.y * w1 + pc.z * w2 + pc.w * w3;
            oa3 += pd.x * w0 + pd.y * w1 + pd.z * w2 + pd.w * w3;
        }
        __syncthreads();
    }
    // reduce partial outputs over 4 s-groups via aux
    aux[sg * 256 + 0 * 64 + d] = oa0;
    aux[sg * 256 + 1 * 64 + d] = oa1;
    aux[sg * 256 + 2 * 64 + d] = oa2;
    aux[sg * 256 + 3 * 64 + d] = oa3;
    __syncthreads();
    {
        int g2 = t >> 6, d2 = t & 63;
        float oo = aux[0 * 256 + g2 * 64 + d2] + aux[1 * 256 + g2 * 64 + d2]
                 + aux[2 * 256 + g2 * 64 + d2] + aux[3 * 256 + g2 * 64 + d2];
        g_pout[(size_t)(pbase + g2) * HD_ + d2] = oo;
    }
    if (t < G_) { g_pmax[pbase + t] = gmax[t]; g_psum[pbase + t] = gsum[t]; }
}

// ---------------- combine splits: one CTA per (kv, b) ----------------
__global__ __launch_bounds__(256) void attn_combine_kernel()
{
    int kv = blockIdx.x, b = blockIdx.y;
    int t = threadIdx.x, g = t >> 6, d = t & 63;
    int base = (b * NKV_ + kv) * SPLIT_ * G_;

    float mi[SPLIT_];
    float M = -1e30f;
#pragma unroll
    for (int i = 0; i < SPLIT_; i++) {
        mi[i] = g_pmax[base + i * G_ + g];
        M = fmaxf(M, mi[i]);
    }
    float denom = 0.f, numer = 0.f;
#pragma unroll
    for (int i = 0; i < SPLIT_; i++) {
        float wgt = __expf(mi[i] - M);
        denom += wgt * g_psum[base + i * G_ + g];
        numer += wgt * g_pout[(size_t)(base + i * G_ + g) * HD_ + d];
    }
    g_att[(size_t)b * (NH_ * HD_) + (kv * G_ + g) * HD_ + d] = numer / denom;
}

// ---------------- launch: kernel launches ONLY ----------------
extern "C" void kernel_launch(void* const* d_in, const int* in_sizes, int n_in,
                              void* d_out, int out_size)
{
    const float* hidden    = (const float*)d_in[0];
    const int*   positions = (const int*)  d_in[1];
    const int*   ctxlens   = (const int*)  d_in[2];
    // d_in[3] slot_mapping unused: phys(ctx-1) == slot, new k/v read directly
    const int*   btab      = (const int*)  d_in[4];
    const float* kc        = (const float*)d_in[5];
    const float* vc        = (const float*)d_in[6];
    const float* wqkv      = (const float*)d_in[7];
    const float* wout      = (const float*)d_in[8];
    const float* qlw       = (const float*)d_in[9];
    const float* klw       = (const float*)d_in[10];
    float* out = (float*)d_out;

    gemm_qkv_kernel<<<dim3(12, 24), 256>>>(hidden, wqkv);
    reduce_qkv_kernel<<<192, 256>>>();
    prep_kernel<<<B_, 256>>>(positions, qlw, klw);
    attn_split_kernel<<<dim3(NKV_, B_, SPLIT_), 256>>>(kc, vc, ctxlens, btab);
    attn_combine_kernel<<<dim3(NKV_, B_), 256>>>();
    gemm_out_kernel<<<dim3(8, 36), 256>>>(wout);
    reduce_out_kernel<<<128, 256>>>(out);
}